// round 13
// baseline (speedup 1.0000x reference)
#include <cuda_runtime.h>
#include <cuda_bf16.h>
#include <math.h>

typedef unsigned long long ull_t;
typedef unsigned int u32;

#define B_  4
#define S_  2048
#define D_  1024
#define H_  16
#define HD_ 64
#define M_  (B_*S_)   // 8192

// ---------------- scratch (__device__ globals: allocation-free rule) ----------
__device__ __nv_bfloat16 g_Qh[(size_t)M_*D_];
__device__ __nv_bfloat16 g_Ql[(size_t)M_*D_];
__device__ __nv_bfloat16 g_Kh[(size_t)M_*D_];
__device__ __nv_bfloat16 g_Kl[(size_t)M_*D_];
__device__ __nv_bfloat16 g_Vh[(size_t)M_*D_];
__device__ __nv_bfloat16 g_Vl[(size_t)M_*D_];
__device__ __nv_bfloat16 g_Ah[(size_t)M_*D_];
__device__ __nv_bfloat16 g_Al[(size_t)M_*D_];
__device__ __nv_bfloat16 g_Wh[(size_t)D_*D_];
__device__ __nv_bfloat16 g_Wl[(size_t)D_*D_];
__device__ __nv_bfloat16 g_Oh[(size_t)M_*D_];
__device__ __nv_bfloat16 g_Ol[(size_t)M_*D_];

// ---------------- baseline-PTX tensor-core helpers (sm_80+, works on sm_103) --
__device__ __forceinline__ u32 smem_u32(const void* p) {
    u32 a; asm("{ .reg .u64 t; cvta.to.shared.u64 t, %1; cvt.u32.u64 %0, t; }" : "=r"(a) : "l"(p));
    return a;
}
__device__ __forceinline__ void ldm_x4(u32* r, u32 addr) {
    asm volatile("ldmatrix.sync.aligned.m8n8.x4.shared.b16 {%0,%1,%2,%3}, [%4];"
        : "=r"(r[0]), "=r"(r[1]), "=r"(r[2]), "=r"(r[3]) : "r"(addr));
}
__device__ __forceinline__ void ldm_x4t(u32* r, u32 addr) {
    asm volatile("ldmatrix.sync.aligned.m8n8.x4.trans.shared.b16 {%0,%1,%2,%3}, [%4];"
        : "=r"(r[0]), "=r"(r[1]), "=r"(r[2]), "=r"(r[3]) : "r"(addr));
}
__device__ __forceinline__ void mma16816(float* d, const u32* a, u32 b0, u32 b1) {
    asm volatile("mma.sync.aligned.m16n8k16.row.col.f32.bf16.bf16.f32 "
        "{%0,%1,%2,%3}, {%4,%5,%6,%7}, {%8,%9}, {%0,%1,%2,%3};"
        : "+f"(d[0]), "+f"(d[1]), "+f"(d[2]), "+f"(d[3])
        : "r"(a[0]), "r"(a[1]), "r"(a[2]), "r"(a[3]), "r"(b0), "r"(b1));
}
#define CP_ASYNC(dst, src) asm volatile("cp.async.cg.shared.global [%0], [%1], 16;" :: "r"(dst), "l"(src) : "memory")
#define CP_COMMIT()  asm volatile("cp.async.commit_group;" ::: "memory")
#define CP_WAIT(n)   asm volatile("cp.async.wait_group %0;" :: "n"(n) : "memory")

__device__ __forceinline__ float ex2f(float x) {
    float y; asm("ex2.approx.f32 %0, %1;" : "=f"(y) : "f"(x)); return y;
}
// pack two floats into bf16x2 (lo in low half, hi in high half)
__device__ __forceinline__ u32 bpack(float lo, float hi) {
    u32 r; asm("cvt.rn.bf16x2.f32 %0, %1, %2;" : "=r"(r) : "f"(hi), "f"(lo)); return r;
}
__device__ __forceinline__ float bf16rt(float x) {   // round-trip through bf16
    return __bfloat162float(__float2bfloat16(x));
}

// =====================================================================
// fp32 -> bf16 hi/lo split
// =====================================================================
__global__ void split_bf16_kernel(const float* __restrict__ x,
                                  __nv_bfloat16* __restrict__ hi,
                                  __nv_bfloat16* __restrict__ lo, int n4)
{
    int i = blockIdx.x * blockDim.x + threadIdx.x;
    if (i >= n4) return;
    float4 v = ((const float4*)x)[i];
    float f[4] = { v.x, v.y, v.z, v.w };
    union { __nv_bfloat16 b[4]; uint2 u; } Hh, Ll;
    #pragma unroll
    for (int j = 0; j < 4; j++) {
        __nv_bfloat16 h = __float2bfloat16(f[j]);
        Hh.b[j] = h;
        Ll.b[j] = __float2bfloat16(f[j] - __bfloat162float(h));
    }
    ((uint2*)hi)[i] = Hh.u;
    ((uint2*)lo)[i] = Ll.u;
}

// =====================================================================
// HMMA GEMM (mma.sync bf16, hi/lo 3-pass)
// MODE 0: C=[M_,D_] fp32 + bias.  MODE 1: bf16 hi/lo -> [B,H,S,HD].
// =====================================================================
#define SROW 40
#define TILEB (128 * SROW * 2)
#define BUFB  (4 * TILEB)
#define GEMM_SMEM (2 * BUFB + 128)

template<int MODE>
__global__ __launch_bounds__(256, 1)
void gemm_mm(const __nv_bfloat16* __restrict__ Ah, const __nv_bfloat16* __restrict__ Al,
             const __nv_bfloat16* __restrict__ Bh, const __nv_bfloat16* __restrict__ Bl,
             const float* __restrict__ bias, float* __restrict__ C,
             __nv_bfloat16* __restrict__ Ch, __nv_bfloat16* __restrict__ Cl)
{
    extern __shared__ char smem[];
    const u32 sbase = (smem_u32(smem) + 127) & ~127u;

    const int t = threadIdx.x;
    const int l = t & 31;
    const int warp = t >> 5;
    const int wm = warp >> 2, wn = warp & 3;
    const int m0 = blockIdx.y * 128;
    const int n0 = blockIdx.x * 128;

    const __nv_bfloat16* gp0 = Ah + (size_t)m0 * D_;
    const __nv_bfloat16* gp1 = Al + (size_t)m0 * D_;
    const __nv_bfloat16* gp2 = Bh + (size_t)n0 * D_;
    const __nv_bfloat16* gp3 = Bl + (size_t)n0 * D_;

    const u32 aoff = ((u32)(wm*64 + ((l & 7) + ((l >> 3) & 1) * 8)) * SROW + ((l >> 4) * 8)) * 2;
    const u32 boff = ((u32)(wn*32 + ((l & 7) + ((l >> 4) & 1) * 8)) * SROW + (((l >> 3) & 1) * 8)) * 2;

    float acc[4][4][4];
    #pragma unroll
    for (int i = 0; i < 4; i++)
        #pragma unroll
        for (int j = 0; j < 4; j++)
            #pragma unroll
            for (int q = 0; q < 4; q++) acc[i][j][q] = 0.f;

    auto cp_chunk = [&](int kc, int bufsel) {
        u32 db = sbase + (u32)bufsel * BUFB;
        #pragma unroll
        for (int i = 0; i < 8; i++) {
            int idx = t + (i & 1) * 256;
            int r = idx >> 2, c = idx & 3;
            size_t go = (size_t)r * D_ + kc + c * 8;
            u32 dst = db + (u32)(i >> 1) * TILEB + (u32)(r * SROW + c * 8) * 2;
            const __nv_bfloat16* src = (i < 2) ? gp0 : (i < 4) ? gp1 : (i < 6) ? gp2 : gp3;
            CP_ASYNC(dst, src + go);
        }
    };

    cp_chunk(0, 0);
    CP_COMMIT();

    const int NCH = D_ / 32;
    for (int kt = 0; kt < NCH; kt++) {
        int buf = kt & 1;
        if (kt + 1 < NCH) {
            cp_chunk((kt + 1) * 32, buf ^ 1);
            CP_COMMIT();
            CP_WAIT(1);
        } else {
            CP_WAIT(0);
        }
        __syncthreads();

        u32 aH = sbase + (u32)buf * BUFB;
        u32 bH = aH + 2 * TILEB;

        #pragma unroll
        for (int ks = 0; ks < 2; ks++) {
            u32 ah[4][4], al[4][4], bh[2][4], bl[2][4];
            #pragma unroll
            for (int mt = 0; mt < 4; mt++) {
                u32 ad = aH + aoff + (u32)(mt * 16 * SROW + ks * 16) * 2;
                ldm_x4(ah[mt], ad);
                ldm_x4(al[mt], ad + TILEB);
            }
            #pragma unroll
            for (int nt = 0; nt < 2; nt++) {
                u32 bd = bH + boff + (u32)(nt * 16 * SROW + ks * 16) * 2;
                ldm_x4(bh[nt], bd);
                ldm_x4(bl[nt], bd + TILEB);
            }
            #pragma unroll
            for (int mt = 0; mt < 4; mt++)
                #pragma unroll
                for (int j = 0; j < 4; j++) {
                    u32 h0 = bh[j >> 1][(j & 1) * 2], h1 = bh[j >> 1][(j & 1) * 2 + 1];
                    u32 l0 = bl[j >> 1][(j & 1) * 2], l1 = bl[j >> 1][(j & 1) * 2 + 1];
                    mma16816(acc[mt][j], ah[mt], h0, h1);
                    mma16816(acc[mt][j], al[mt], h0, h1);
                    mma16816(acc[mt][j], ah[mt], l0, l1);
                }
        }
        __syncthreads();
    }

    const int r0 = l >> 2, cp2 = (l & 3) * 2;
    #pragma unroll
    for (int mt = 0; mt < 4; mt++)
        #pragma unroll
        for (int j = 0; j < 4; j++) {
            int m = m0 + wm * 64 + mt * 16 + r0;
            int n = n0 + wn * 32 + j * 8 + cp2;
            if (MODE == 0) {
                float2 bb = *(const float2*)&bias[n];
                *(float2*)&C[(size_t)m * D_ + n] =
                    make_float2(acc[mt][j][0] + bb.x, acc[mt][j][1] + bb.y);
                *(float2*)&C[(size_t)(m + 8) * D_ + n] =
                    make_float2(acc[mt][j][2] + bb.x, acc[mt][j][3] + bb.y);
            } else {
                int h = n >> 6, d = n & 63;
                int b = m >> 11, s = m & 2047;
                size_t o = (((size_t)(b * H_ + h)) * S_ + s) * HD_ + d;
                #pragma unroll
                for (int rr = 0; rr < 2; rr++) {
                    float x0 = acc[mt][j][rr*2], x1 = acc[mt][j][rr*2+1];
                    float h0 = bf16rt(x0), h1 = bf16rt(x1);
                    size_t oo = o + (size_t)rr * 8 * HD_;
                    *(u32*)&Ch[oo] = bpack(h0, h1);
                    *(u32*)&Cl[oo] = bpack(x0 - h0, x1 - h1);
                }
            }
        }
}

// =====================================================================
// Tensor-core flash attention, bf16 hi/lo 3-pass.
// CTA: 128 q-rows of one (b,h). 8 warps x 16 q-rows. K-tiles of 64 keys.
// =====================================================================
#define SP   72                       // padded bf16 row stride
#define QT   (128 * SP * 2)           // 18432 B per Q array
#define KVT  (64 * SP * 2)            // 9216 B per K/V array
#define KVBUF (4 * KVT)               // 36864 B (Kh,Kl,Vh,Vl)
#define ATTN_SMEM (2 * QT + 2 * KVBUF + 128)   // 110720 B
#define CEXP 0.18033688011112042f     // 0.125 * log2(e)

__global__ __launch_bounds__(256, 1)
void attn_tc(const __nv_bfloat16* __restrict__ Qh, const __nv_bfloat16* __restrict__ Ql,
             const __nv_bfloat16* __restrict__ Kh, const __nv_bfloat16* __restrict__ Kl,
             const __nv_bfloat16* __restrict__ Vh, const __nv_bfloat16* __restrict__ Vl,
             __nv_bfloat16* __restrict__ Oh, __nv_bfloat16* __restrict__ Ol)
{
    extern __shared__ char smem[];
    const u32 sbase = (smem_u32(smem) + 127) & ~127u;
    const u32 sQh = sbase, sQl = sbase + QT, sKV = sbase + 2 * QT;

    const int t = threadIdx.x;
    const int l = t & 31;
    const int w = t >> 5;
    const int bh = blockIdx.y;
    const int q0 = blockIdx.x * 128;

    const __nv_bfloat16* qhp = Qh + ((size_t)bh * S_ + q0) * HD_;
    const __nv_bfloat16* qlp = Ql + ((size_t)bh * S_ + q0) * HD_;

    // Q load (both halves): 128 rows x 64 elems
    #pragma unroll
    for (int i = 0; i < 4; i++) {
        int idx = t + i * 256;
        int r = idx >> 3, c = idx & 7;
        u32 so = (u32)((r * SP + c * 8) * 2);
        size_t go = (size_t)r * HD_ + c * 8;
        CP_ASYNC(sQh + so, qhp + go);
        CP_ASYNC(sQl + so, qlp + go);
    }

    auto cp_kv = [&](int kt, int bufsel) {
        u32 db = sKV + (u32)bufsel * KVBUF;
        size_t gbase = (size_t)bh * S_ * HD_ + (size_t)kt * 64 * HD_;
        #pragma unroll
        for (int i = 0; i < 2; i++) {
            int idx = t + i * 256;
            int r = idx >> 3, c = idx & 7;
            u32 so = (u32)((r * SP + c * 8) * 2);
            size_t go = gbase + (size_t)r * HD_ + c * 8;
            CP_ASYNC(db + 0 * KVT + so, Kh + go);
            CP_ASYNC(db + 1 * KVT + so, Kl + go);
            CP_ASYNC(db + 2 * KVT + so, Vh + go);
            CP_ASYNC(db + 3 * KVT + so, Vl + go);
        }
    };

    cp_kv(0, 0);
    CP_COMMIT();

    // per-lane fragment offsets (bytes)
    const u32 aoff = (u32)(((w * 16 + (l & 15)) * SP + (l >> 4) * 8) * 2);
    const u32 koff = (u32)((((l & 7) + ((l >> 4) & 1) * 8) * SP + ((l >> 3) & 1) * 8) * 2);
    const u32 voff = (u32)((((l & 7) + ((l >> 3) & 1) * 8) * SP + ((l >> 4) & 1) * 8) * 2);

    float acc_o[8][4];
    #pragma unroll
    for (int i = 0; i < 8; i++)
        #pragma unroll
        for (int q = 0; q < 4; q++) acc_o[i][q] = 0.f;
    float mi0 = -1e30f, mi1 = -1e30f, li0 = 0.f, li1 = 0.f;

    const int NT = S_ / 64;   // 32
    for (int kt = 0; kt < NT; kt++) {
        int buf = kt & 1;
        if (kt + 1 < NT) {
            cp_kv(kt + 1, buf ^ 1);
            CP_COMMIT();
            CP_WAIT(1);
        } else {
            CP_WAIT(0);
        }
        __syncthreads();

        u32 kb = sKV + (u32)buf * KVBUF;

        // ---- S = Q K^T, 3-pass hi/lo. s[j] = n8 tile j over 64 keys.
        float s[8][4];
        #pragma unroll
        for (int j = 0; j < 8; j++)
            #pragma unroll
            for (int q = 0; q < 4; q++) s[j][q] = 0.f;

        #pragma unroll
        for (int ks = 0; ks < 4; ks++) {
            u32 qa[4], ql4[4], khf[4][4], klf[4][4];
            u32 ad = sQh + aoff + (u32)(ks * 32);
            ldm_x4(qa, ad);
            ldm_x4(ql4, ad + QT);
            #pragma unroll
            for (int nb = 0; nb < 4; nb++) {
                u32 bd = kb + koff + (u32)((nb * 16 * SP) * 2 + ks * 32);
                ldm_x4(khf[nb], bd);
                ldm_x4(klf[nb], bd + KVT);
            }
            #pragma unroll
            for (int j = 0; j < 8; j++) {
                u32 h0 = khf[j >> 1][(j & 1) * 2], h1 = khf[j >> 1][(j & 1) * 2 + 1];
                u32 l0 = klf[j >> 1][(j & 1) * 2], l1 = klf[j >> 1][(j & 1) * 2 + 1];
                mma16816(s[j], qa, h0, h1);
                mma16816(s[j], ql4, h0, h1);
                mma16816(s[j], qa, l0, l1);
            }
        }

        // ---- online softmax (lane owns rows r=l/4 and r+8; quad = 4 lanes/row)
        float mx0 = -1e30f, mx1 = -1e30f;
        #pragma unroll
        for (int j = 0; j < 8; j++) {
            mx0 = fmaxf(mx0, fmaxf(s[j][0], s[j][1]));
            mx1 = fmaxf(mx1, fmaxf(s[j][2], s[j][3]));
        }
        mx0 = fmaxf(mx0, __shfl_xor_sync(0xffffffffu, mx0, 1));
        mx0 = fmaxf(mx0, __shfl_xor_sync(0xffffffffu, mx0, 2));
        mx1 = fmaxf(mx1, __shfl_xor_sync(0xffffffffu, mx1, 1));
        mx1 = fmaxf(mx1, __shfl_xor_sync(0xffffffffu, mx1, 2));
        float mn0 = fmaxf(mi0, mx0), mn1 = fmaxf(mi1, mx1);
        float corr0 = ex2f(CEXP * (mi0 - mn0));
        float corr1 = ex2f(CEXP * (mi1 - mn1));
        mi0 = mn0; mi1 = mn1;

        float rs0 = 0.f, rs1 = 0.f;
        #pragma unroll
        for (int j = 0; j < 8; j++) {
            s[j][0] = ex2f(CEXP * (s[j][0] - mn0));
            s[j][1] = ex2f(CEXP * (s[j][1] - mn0));
            s[j][2] = ex2f(CEXP * (s[j][2] - mn1));
            s[j][3] = ex2f(CEXP * (s[j][3] - mn1));
            rs0 += s[j][0] + s[j][1];
            rs1 += s[j][2] + s[j][3];
        }
        rs0 += __shfl_xor_sync(0xffffffffu, rs0, 1);
        rs0 += __shfl_xor_sync(0xffffffffu, rs0, 2);
        rs1 += __shfl_xor_sync(0xffffffffu, rs1, 1);
        rs1 += __shfl_xor_sync(0xffffffffu, rs1, 2);
        li0 = li0 * corr0 + rs0;
        li1 = li1 * corr1 + rs1;

        #pragma unroll
        for (int i = 0; i < 8; i++) {
            acc_o[i][0] *= corr0; acc_o[i][1] *= corr0;
            acc_o[i][2] *= corr1; acc_o[i][3] *= corr1;
        }

        // ---- O += P V, 3-pass hi/lo (P from registers, V via ldmatrix.trans)
        u32 vb2 = kb + 2 * KVT + voff;
        #pragma unroll
        for (int ks = 0; ks < 4; ks++) {
            int j0 = 2 * ks, j1 = 2 * ks + 1;
            float h00 = bf16rt(s[j0][0]), h01 = bf16rt(s[j0][1]);
            float h02 = bf16rt(s[j0][2]), h03 = bf16rt(s[j0][3]);
            float h10 = bf16rt(s[j1][0]), h11 = bf16rt(s[j1][1]);
            float h12 = bf16rt(s[j1][2]), h13 = bf16rt(s[j1][3]);
            u32 pa[4], pl4[4];
            pa[0] = bpack(h00, h01);  pa[1] = bpack(h02, h03);
            pa[2] = bpack(h10, h11);  pa[3] = bpack(h12, h13);
            pl4[0] = bpack(s[j0][0]-h00, s[j0][1]-h01);
            pl4[1] = bpack(s[j0][2]-h02, s[j0][3]-h03);
            pl4[2] = bpack(s[j1][0]-h10, s[j1][1]-h11);
            pl4[3] = bpack(s[j1][2]-h12, s[j1][3]-h13);

            u32 vhf[4][4], vlf[4][4];
            #pragma unroll
            for (int nb = 0; nb < 4; nb++) {
                u32 vd = vb2 + (u32)((ks * 16 * SP) * 2 + nb * 32);
                ldm_x4t(vhf[nb], vd);
                ldm_x4t(vlf[nb], vd + KVT);
            }
            #pragma unroll
            for (int nt = 0; nt < 8; nt++) {
                u32 h0 = vhf[nt >> 1][(nt & 1) * 2], h1 = vhf[nt >> 1][(nt & 1) * 2 + 1];
                u32 l0 = vlf[nt >> 1][(nt & 1) * 2], l1 = vlf[nt >> 1][(nt & 1) * 2 + 1];
                mma16816(acc_o[nt], pa, h0, h1);
                mma16816(acc_o[nt], pl4, h0, h1);
                mma16816(acc_o[nt], pa, l0, l1);
            }
        }
        __syncthreads();
    }

    // ---- epilogue: normalize, write bf16 hi/lo O in [M_, D_] layout
    float inv0 = 1.f / li0, inv1 = 1.f / li1;
    int b = bh >> 4, h = bh & 15;
    int row0 = q0 + w * 16 + (l >> 2);
    size_t base0 = ((size_t)(b * S_ + row0)) * D_ + h * HD_ + (l & 3) * 2;
    size_t base1 = base0 + (size_t)8 * D_;
    #pragma unroll
    for (int nt = 0; nt < 8; nt++) {
        float o0 = acc_o[nt][0] * inv0, o1 = acc_o[nt][1] * inv0;
        float o2 = acc_o[nt][2] * inv1, o3 = acc_o[nt][3] * inv1;
        float p0 = bf16rt(o0), p1 = bf16rt(o1), p2 = bf16rt(o2), p3 = bf16rt(o3);
        *(u32*)&Oh[base0 + nt * 8] = bpack(p0, p1);
        *(u32*)&Ol[base0 + nt * 8] = bpack(o0 - p0, o1 - p1);
        *(u32*)&Oh[base1 + nt * 8] = bpack(p2, p3);
        *(u32*)&Ol[base1 + nt * 8] = bpack(o2 - p2, o3 - p3);
    }
}

// =====================================================================
extern "C" void kernel_launch(void* const* d_in, const int* in_sizes, int n_in,
                              void* d_out, int out_size)
{
    const float* query = (const float*)d_in[0];
    const float* key   = (const float*)d_in[1];
    const float* value = (const float*)d_in[2];
    const float* wq    = (const float*)d_in[3];
    const float* wk    = (const float*)d_in[4];
    const float* wv    = (const float*)d_in[5];
    const float* wo    = (const float*)d_in[6];
    const float* bo    = (const float*)d_in[7];
    float* out = (float*)d_out;

    __nv_bfloat16 *Qhp, *Qlp, *Khp, *Klp, *Vhp, *Vlp;
    __nv_bfloat16 *Ahp, *Alp, *Whp, *Wlp, *Ohp, *Olp;
    cudaGetSymbolAddress((void**)&Qhp, g_Qh);
    cudaGetSymbolAddress((void**)&Qlp, g_Ql);
    cudaGetSymbolAddress((void**)&Khp, g_Kh);
    cudaGetSymbolAddress((void**)&Klp, g_Kl);
    cudaGetSymbolAddress((void**)&Vhp, g_Vh);
    cudaGetSymbolAddress((void**)&Vlp, g_Vl);
    cudaGetSymbolAddress((void**)&Ahp, g_Ah);
    cudaGetSymbolAddress((void**)&Alp, g_Al);
    cudaGetSymbolAddress((void**)&Whp, g_Wh);
    cudaGetSymbolAddress((void**)&Wlp, g_Wl);
    cudaGetSymbolAddress((void**)&Ohp, g_Oh);
    cudaGetSymbolAddress((void**)&Olp, g_Ol);

    cudaFuncSetAttribute(gemm_mm<0>, cudaFuncAttributeMaxDynamicSharedMemorySize, GEMM_SMEM);
    cudaFuncSetAttribute(gemm_mm<1>, cudaFuncAttributeMaxDynamicSharedMemorySize, GEMM_SMEM);
    cudaFuncSetAttribute(attn_tc, cudaFuncAttributeMaxDynamicSharedMemorySize, ATTN_SMEM);

    const int nAct4 = (M_ * D_) / 4;
    const int nW4   = (D_ * D_) / 4;
    dim3 gg(D_ / 128, M_ / 128);   // (8, 64)

    // Q projection -> bf16 hi/lo [B,H,S,HD]
    split_bf16_kernel<<<nAct4 / 256, 256>>>(query, Ahp, Alp, nAct4);
    split_bf16_kernel<<<nW4 / 256, 256>>>(wq, Whp, Wlp, nW4);
    gemm_mm<1><<<gg, 256, GEMM_SMEM>>>(Ahp, Alp, Whp, Wlp, nullptr, nullptr, Qhp, Qlp);
    // K projection
    split_bf16_kernel<<<nAct4 / 256, 256>>>(key, Ahp, Alp, nAct4);
    split_bf16_kernel<<<nW4 / 256, 256>>>(wk, Whp, Wlp, nW4);
    gemm_mm<1><<<gg, 256, GEMM_SMEM>>>(Ahp, Alp, Whp, Wlp, nullptr, nullptr, Khp, Klp);
    // V projection
    split_bf16_kernel<<<nAct4 / 256, 256>>>(value, Ahp, Alp, nAct4);
    split_bf16_kernel<<<nW4 / 256, 256>>>(wv, Whp, Wlp, nW4);
    gemm_mm<1><<<gg, 256, GEMM_SMEM>>>(Ahp, Alp, Whp, Wlp, nullptr, nullptr, Vhp, Vlp);

    // tensor-core attention (writes bf16 hi/lo O)
    attn_tc<<<dim3(S_ / 128, B_ * H_), 256, ATTN_SMEM>>>(
        Qhp, Qlp, Khp, Klp, Vhp, Vlp, Ohp, Olp);

    // output projection + bias
    split_bf16_kernel<<<nW4 / 256, 256>>>(wo, Whp, Wlp, nW4);
    gemm_mm<0><<<gg, 256, GEMM_SMEM>>>(Ohp, Olp, Whp, Wlp, bo, out, nullptr, nullptr);
}

// round 14
// speedup vs baseline: 1.0007x; 1.0007x over previous
#include <cuda_runtime.h>
#include <cuda_bf16.h>
#include <math.h>

typedef unsigned long long ull_t;
typedef unsigned int u32;

#define B_  4
#define S_  2048
#define D_  1024
#define H_  16
#define HD_ 64
#define M_  (B_*S_)   // 8192

// ---------------- scratch (__device__ globals: allocation-free rule) ----------
__device__ __nv_bfloat16 g_Qh[(size_t)M_*D_];
__device__ __nv_bfloat16 g_Ql[(size_t)M_*D_];
__device__ __nv_bfloat16 g_Kh[(size_t)M_*D_];
__device__ __nv_bfloat16 g_Kl[(size_t)M_*D_];
__device__ __nv_bfloat16 g_Vh[(size_t)M_*D_];
__device__ __nv_bfloat16 g_Vl[(size_t)M_*D_];
__device__ __nv_bfloat16 g_Ah[(size_t)M_*D_];
__device__ __nv_bfloat16 g_Al[(size_t)M_*D_];
__device__ __nv_bfloat16 g_Wh[(size_t)D_*D_];
__device__ __nv_bfloat16 g_Wl[(size_t)D_*D_];
__device__ __nv_bfloat16 g_Oh[(size_t)M_*D_];
__device__ __nv_bfloat16 g_Ol[(size_t)M_*D_];

// ---------------- baseline-PTX tensor-core helpers (sm_80+, works on sm_103) --
__device__ __forceinline__ u32 smem_u32(const void* p) {
    u32 a; asm("{ .reg .u64 t; cvta.to.shared.u64 t, %1; cvt.u32.u64 %0, t; }" : "=r"(a) : "l"(p));
    return a;
}
__device__ __forceinline__ void ldm_x4(u32* r, u32 addr) {
    asm volatile("ldmatrix.sync.aligned.m8n8.x4.shared.b16 {%0,%1,%2,%3}, [%4];"
        : "=r"(r[0]), "=r"(r[1]), "=r"(r[2]), "=r"(r[3]) : "r"(addr));
}
__device__ __forceinline__ void ldm_x4t(u32* r, u32 addr) {
    asm volatile("ldmatrix.sync.aligned.m8n8.x4.trans.shared.b16 {%0,%1,%2,%3}, [%4];"
        : "=r"(r[0]), "=r"(r[1]), "=r"(r[2]), "=r"(r[3]) : "r"(addr));
}
__device__ __forceinline__ void mma16816(float* d, const u32* a, u32 b0, u32 b1) {
    asm volatile("mma.sync.aligned.m16n8k16.row.col.f32.bf16.bf16.f32 "
        "{%0,%1,%2,%3}, {%4,%5,%6,%7}, {%8,%9}, {%0,%1,%2,%3};"
        : "+f"(d[0]), "+f"(d[1]), "+f"(d[2]), "+f"(d[3])
        : "r"(a[0]), "r"(a[1]), "r"(a[2]), "r"(a[3]), "r"(b0), "r"(b1));
}
#define CP_ASYNC(dst, src) asm volatile("cp.async.cg.shared.global [%0], [%1], 16;" :: "r"(dst), "l"(src) : "memory")
#define CP_COMMIT()  asm volatile("cp.async.commit_group;" ::: "memory")
#define CP_WAIT(n)   asm volatile("cp.async.wait_group %0;" :: "n"(n) : "memory")

__device__ __forceinline__ float ex2f(float x) {
    float y; asm("ex2.approx.f32 %0, %1;" : "=f"(y) : "f"(x)); return y;
}
// pack two floats into bf16x2 (lo in low half, hi in high half)
__device__ __forceinline__ u32 bpack(float lo, float hi) {
    u32 r; asm("cvt.rn.bf16x2.f32 %0, %1, %2;" : "=r"(r) : "f"(hi), "f"(lo)); return r;
}
__device__ __forceinline__ float bf16rt(float x) {   // round-trip through bf16
    return __bfloat162float(__float2bfloat16(x));
}

// =====================================================================
// fp32 -> bf16 hi/lo split
// =====================================================================
__global__ void split_bf16_kernel(const float* __restrict__ x,
                                  __nv_bfloat16* __restrict__ hi,
                                  __nv_bfloat16* __restrict__ lo, int n4)
{
    int i = blockIdx.x * blockDim.x + threadIdx.x;
    if (i >= n4) return;
    float4 v = ((const float4*)x)[i];
    float f[4] = { v.x, v.y, v.z, v.w };
    union { __nv_bfloat16 b[4]; uint2 u; } Hh, Ll;
    #pragma unroll
    for (int j = 0; j < 4; j++) {
        __nv_bfloat16 h = __float2bfloat16(f[j]);
        Hh.b[j] = h;
        Ll.b[j] = __float2bfloat16(f[j] - __bfloat162float(h));
    }
    ((uint2*)hi)[i] = Hh.u;
    ((uint2*)lo)[i] = Ll.u;
}

// =====================================================================
// HMMA GEMM (mma.sync bf16, hi/lo 3-pass)
// MODE 0: C=[M_,D_] fp32 + bias.  MODE 1: bf16 hi/lo -> [B,H,S,HD].
// =====================================================================
#define SROW 40
#define TILEB (128 * SROW * 2)
#define BUFB  (4 * TILEB)
#define GEMM_SMEM (2 * BUFB + 128)

template<int MODE>
__global__ __launch_bounds__(256, 1)
void gemm_mm(const __nv_bfloat16* __restrict__ Ah, const __nv_bfloat16* __restrict__ Al,
             const __nv_bfloat16* __restrict__ Bh, const __nv_bfloat16* __restrict__ Bl,
             const float* __restrict__ bias, float* __restrict__ C,
             __nv_bfloat16* __restrict__ Ch, __nv_bfloat16* __restrict__ Cl)
{
    extern __shared__ char smem[];
    const u32 sbase = (smem_u32(smem) + 127) & ~127u;

    const int t = threadIdx.x;
    const int l = t & 31;
    const int warp = t >> 5;
    const int wm = warp >> 2, wn = warp & 3;
    const int m0 = blockIdx.y * 128;
    const int n0 = blockIdx.x * 128;

    const __nv_bfloat16* gp0 = Ah + (size_t)m0 * D_;
    const __nv_bfloat16* gp1 = Al + (size_t)m0 * D_;
    const __nv_bfloat16* gp2 = Bh + (size_t)n0 * D_;
    const __nv_bfloat16* gp3 = Bl + (size_t)n0 * D_;

    const u32 aoff = ((u32)(wm*64 + ((l & 7) + ((l >> 3) & 1) * 8)) * SROW + ((l >> 4) * 8)) * 2;
    const u32 boff = ((u32)(wn*32 + ((l & 7) + ((l >> 4) & 1) * 8)) * SROW + (((l >> 3) & 1) * 8)) * 2;

    float acc[4][4][4];
    #pragma unroll
    for (int i = 0; i < 4; i++)
        #pragma unroll
        for (int j = 0; j < 4; j++)
            #pragma unroll
            for (int q = 0; q < 4; q++) acc[i][j][q] = 0.f;

    auto cp_chunk = [&](int kc, int bufsel) {
        u32 db = sbase + (u32)bufsel * BUFB;
        #pragma unroll
        for (int i = 0; i < 8; i++) {
            int idx = t + (i & 1) * 256;
            int r = idx >> 2, c = idx & 3;
            size_t go = (size_t)r * D_ + kc + c * 8;
            u32 dst = db + (u32)(i >> 1) * TILEB + (u32)(r * SROW + c * 8) * 2;
            const __nv_bfloat16* src = (i < 2) ? gp0 : (i < 4) ? gp1 : (i < 6) ? gp2 : gp3;
            CP_ASYNC(dst, src + go);
        }
    };

    cp_chunk(0, 0);
    CP_COMMIT();

    const int NCH = D_ / 32;
    for (int kt = 0; kt < NCH; kt++) {
        int buf = kt & 1;
        if (kt + 1 < NCH) {
            cp_chunk((kt + 1) * 32, buf ^ 1);
            CP_COMMIT();
            CP_WAIT(1);
        } else {
            CP_WAIT(0);
        }
        __syncthreads();

        u32 aH = sbase + (u32)buf * BUFB;
        u32 bH = aH + 2 * TILEB;

        #pragma unroll
        for (int ks = 0; ks < 2; ks++) {
            u32 ah[4][4], al[4][4], bh[2][4], bl[2][4];
            #pragma unroll
            for (int mt = 0; mt < 4; mt++) {
                u32 ad = aH + aoff + (u32)(mt * 16 * SROW + ks * 16) * 2;
                ldm_x4(ah[mt], ad);
                ldm_x4(al[mt], ad + TILEB);
            }
            #pragma unroll
            for (int nt = 0; nt < 2; nt++) {
                u32 bd = bH + boff + (u32)(nt * 16 * SROW + ks * 16) * 2;
                ldm_x4(bh[nt], bd);
                ldm_x4(bl[nt], bd + TILEB);
            }
            #pragma unroll
            for (int mt = 0; mt < 4; mt++)
                #pragma unroll
                for (int j = 0; j < 4; j++) {
                    u32 h0 = bh[j >> 1][(j & 1) * 2], h1 = bh[j >> 1][(j & 1) * 2 + 1];
                    u32 l0 = bl[j >> 1][(j & 1) * 2], l1 = bl[j >> 1][(j & 1) * 2 + 1];
                    mma16816(acc[mt][j], ah[mt], h0, h1);
                    mma16816(acc[mt][j], al[mt], h0, h1);
                    mma16816(acc[mt][j], ah[mt], l0, l1);
                }
        }
        __syncthreads();
    }

    const int r0 = l >> 2, cp2 = (l & 3) * 2;
    #pragma unroll
    for (int mt = 0; mt < 4; mt++)
        #pragma unroll
        for (int j = 0; j < 4; j++) {
            int m = m0 + wm * 64 + mt * 16 + r0;
            int n = n0 + wn * 32 + j * 8 + cp2;
            if (MODE == 0) {
                float2 bb = *(const float2*)&bias[n];
                *(float2*)&C[(size_t)m * D_ + n] =
                    make_float2(acc[mt][j][0] + bb.x, acc[mt][j][1] + bb.y);
                *(float2*)&C[(size_t)(m + 8) * D_ + n] =
                    make_float2(acc[mt][j][2] + bb.x, acc[mt][j][3] + bb.y);
            } else {
                int h = n >> 6, d = n & 63;
                int b = m >> 11, s = m & 2047;
                size_t o = (((size_t)(b * H_ + h)) * S_ + s) * HD_ + d;
                #pragma unroll
                for (int rr = 0; rr < 2; rr++) {
                    float x0 = acc[mt][j][rr*2], x1 = acc[mt][j][rr*2+1];
                    float h0 = bf16rt(x0), h1 = bf16rt(x1);
                    size_t oo = o + (size_t)rr * 8 * HD_;
                    *(u32*)&Ch[oo] = bpack(h0, h1);
                    *(u32*)&Cl[oo] = bpack(x0 - h0, x1 - h1);
                }
            }
        }
}

// =====================================================================
// Tensor-core flash attention, bf16 hi/lo 3-pass.
// CTA: 128 q-rows of one (b,h). 8 warps x 16 q-rows. K-tiles of 64 keys.
// =====================================================================
#define SP   72                       // padded bf16 row stride
#define QT   (128 * SP * 2)           // 18432 B per Q array
#define KVT  (64 * SP * 2)            // 9216 B per K/V array
#define KVBUF (4 * KVT)               // 36864 B (Kh,Kl,Vh,Vl)
#define ATTN_SMEM (2 * QT + 2 * KVBUF + 128)   // 110720 B
#define CEXP 0.18033688011112042f     // 0.125 * log2(e)

__global__ __launch_bounds__(256, 1)
void attn_tc(const __nv_bfloat16* __restrict__ Qh, const __nv_bfloat16* __restrict__ Ql,
             const __nv_bfloat16* __restrict__ Kh, const __nv_bfloat16* __restrict__ Kl,
             const __nv_bfloat16* __restrict__ Vh, const __nv_bfloat16* __restrict__ Vl,
             __nv_bfloat16* __restrict__ Oh, __nv_bfloat16* __restrict__ Ol)
{
    extern __shared__ char smem[];
    const u32 sbase = (smem_u32(smem) + 127) & ~127u;
    const u32 sQh = sbase, sQl = sbase + QT, sKV = sbase + 2 * QT;

    const int t = threadIdx.x;
    const int l = t & 31;
    const int w = t >> 5;
    const int bh = blockIdx.y;
    const int q0 = blockIdx.x * 128;

    const __nv_bfloat16* qhp = Qh + ((size_t)bh * S_ + q0) * HD_;
    const __nv_bfloat16* qlp = Ql + ((size_t)bh * S_ + q0) * HD_;

    // Q load (both halves): 128 rows x 64 elems
    #pragma unroll
    for (int i = 0; i < 4; i++) {
        int idx = t + i * 256;
        int r = idx >> 3, c = idx & 7;
        u32 so = (u32)((r * SP + c * 8) * 2);
        size_t go = (size_t)r * HD_ + c * 8;
        CP_ASYNC(sQh + so, qhp + go);
        CP_ASYNC(sQl + so, qlp + go);
    }

    auto cp_kv = [&](int kt, int bufsel) {
        u32 db = sKV + (u32)bufsel * KVBUF;
        size_t gbase = (size_t)bh * S_ * HD_ + (size_t)kt * 64 * HD_;
        #pragma unroll
        for (int i = 0; i < 2; i++) {
            int idx = t + i * 256;
            int r = idx >> 3, c = idx & 7;
            u32 so = (u32)((r * SP + c * 8) * 2);
            size_t go = gbase + (size_t)r * HD_ + c * 8;
            CP_ASYNC(db + 0 * KVT + so, Kh + go);
            CP_ASYNC(db + 1 * KVT + so, Kl + go);
            CP_ASYNC(db + 2 * KVT + so, Vh + go);
            CP_ASYNC(db + 3 * KVT + so, Vl + go);
        }
    };

    cp_kv(0, 0);
    CP_COMMIT();

    // per-lane fragment offsets (bytes)
    const u32 aoff = (u32)(((w * 16 + (l & 15)) * SP + (l >> 4) * 8) * 2);
    const u32 koff = (u32)((((l & 7) + ((l >> 4) & 1) * 8) * SP + ((l >> 3) & 1) * 8) * 2);
    const u32 voff = (u32)((((l & 7) + ((l >> 3) & 1) * 8) * SP + ((l >> 4) & 1) * 8) * 2);

    float acc_o[8][4];
    #pragma unroll
    for (int i = 0; i < 8; i++)
        #pragma unroll
        for (int q = 0; q < 4; q++) acc_o[i][q] = 0.f;
    float mi0 = -1e30f, mi1 = -1e30f, li0 = 0.f, li1 = 0.f;

    const int NT = S_ / 64;   // 32
    for (int kt = 0; kt < NT; kt++) {
        int buf = kt & 1;
        if (kt + 1 < NT) {
            cp_kv(kt + 1, buf ^ 1);
            CP_COMMIT();
            CP_WAIT(1);
        } else {
            CP_WAIT(0);
        }
        __syncthreads();

        u32 kb = sKV + (u32)buf * KVBUF;

        // ---- S = Q K^T, 3-pass hi/lo. s[j] = n8 tile j over 64 keys.
        float s[8][4];
        #pragma unroll
        for (int j = 0; j < 8; j++)
            #pragma unroll
            for (int q = 0; q < 4; q++) s[j][q] = 0.f;

        #pragma unroll
        for (int ks = 0; ks < 4; ks++) {
            u32 qa[4], ql4[4], khf[4][4], klf[4][4];
            u32 ad = sQh + aoff + (u32)(ks * 32);
            ldm_x4(qa, ad);
            ldm_x4(ql4, ad + QT);
            #pragma unroll
            for (int nb = 0; nb < 4; nb++) {
                u32 bd = kb + koff + (u32)((nb * 16 * SP) * 2 + ks * 32);
                ldm_x4(khf[nb], bd);
                ldm_x4(klf[nb], bd + KVT);
            }
            #pragma unroll
            for (int j = 0; j < 8; j++) {
                u32 h0 = khf[j >> 1][(j & 1) * 2], h1 = khf[j >> 1][(j & 1) * 2 + 1];
                u32 l0 = klf[j >> 1][(j & 1) * 2], l1 = klf[j >> 1][(j & 1) * 2 + 1];
                mma16816(s[j], qa, h0, h1);
                mma16816(s[j], ql4, h0, h1);
                mma16816(s[j], qa, l0, l1);
            }
        }

        // ---- online softmax (lane owns rows r=l/4 and r+8; quad = 4 lanes/row)
        float mx0 = -1e30f, mx1 = -1e30f;
        #pragma unroll
        for (int j = 0; j < 8; j++) {
            mx0 = fmaxf(mx0, fmaxf(s[j][0], s[j][1]));
            mx1 = fmaxf(mx1, fmaxf(s[j][2], s[j][3]));
        }
        mx0 = fmaxf(mx0, __shfl_xor_sync(0xffffffffu, mx0, 1));
        mx0 = fmaxf(mx0, __shfl_xor_sync(0xffffffffu, mx0, 2));
        mx1 = fmaxf(mx1, __shfl_xor_sync(0xffffffffu, mx1, 1));
        mx1 = fmaxf(mx1, __shfl_xor_sync(0xffffffffu, mx1, 2));
        float mn0 = fmaxf(mi0, mx0), mn1 = fmaxf(mi1, mx1);
        float corr0 = ex2f(CEXP * (mi0 - mn0));
        float corr1 = ex2f(CEXP * (mi1 - mn1));
        mi0 = mn0; mi1 = mn1;

        float rs0 = 0.f, rs1 = 0.f;
        #pragma unroll
        for (int j = 0; j < 8; j++) {
            s[j][0] = ex2f(CEXP * (s[j][0] - mn0));
            s[j][1] = ex2f(CEXP * (s[j][1] - mn0));
            s[j][2] = ex2f(CEXP * (s[j][2] - mn1));
            s[j][3] = ex2f(CEXP * (s[j][3] - mn1));
            rs0 += s[j][0] + s[j][1];
            rs1 += s[j][2] + s[j][3];
        }
        rs0 += __shfl_xor_sync(0xffffffffu, rs0, 1);
        rs0 += __shfl_xor_sync(0xffffffffu, rs0, 2);
        rs1 += __shfl_xor_sync(0xffffffffu, rs1, 1);
        rs1 += __shfl_xor_sync(0xffffffffu, rs1, 2);
        li0 = li0 * corr0 + rs0;
        li1 = li1 * corr1 + rs1;

        #pragma unroll
        for (int i = 0; i < 8; i++) {
            acc_o[i][0] *= corr0; acc_o[i][1] *= corr0;
            acc_o[i][2] *= corr1; acc_o[i][3] *= corr1;
        }

        // ---- O += P V, 3-pass hi/lo (P from registers, V via ldmatrix.trans)
        u32 vb2 = kb + 2 * KVT + voff;
        #pragma unroll
        for (int ks = 0; ks < 4; ks++) {
            int j0 = 2 * ks, j1 = 2 * ks + 1;
            float h00 = bf16rt(s[j0][0]), h01 = bf16rt(s[j0][1]);
            float h02 = bf16rt(s[j0][2]), h03 = bf16rt(s[j0][3]);
            float h10 = bf16rt(s[j1][0]), h11 = bf16rt(s[j1][1]);
            float h12 = bf16rt(s[j1][2]), h13 = bf16rt(s[j1][3]);
            u32 pa[4], pl4[4];
            pa[0] = bpack(h00, h01);  pa[1] = bpack(h02, h03);
            pa[2] = bpack(h10, h11);  pa[3] = bpack(h12, h13);
            pl4[0] = bpack(s[j0][0]-h00, s[j0][1]-h01);
            pl4[1] = bpack(s[j0][2]-h02, s[j0][3]-h03);
            pl4[2] = bpack(s[j1][0]-h10, s[j1][1]-h11);
            pl4[3] = bpack(s[j1][2]-h12, s[j1][3]-h13);

            u32 vhf[4][4], vlf[4][4];
            #pragma unroll
            for (int nb = 0; nb < 4; nb++) {
                u32 vd = vb2 + (u32)((ks * 16 * SP) * 2 + nb * 32);
                ldm_x4t(vhf[nb], vd);
                ldm_x4t(vlf[nb], vd + KVT);
            }
            #pragma unroll
            for (int nt = 0; nt < 8; nt++) {
                u32 h0 = vhf[nt >> 1][(nt & 1) * 2], h1 = vhf[nt >> 1][(nt & 1) * 2 + 1];
                u32 l0 = vlf[nt >> 1][(nt & 1) * 2], l1 = vlf[nt >> 1][(nt & 1) * 2 + 1];
                mma16816(acc_o[nt], pa, h0, h1);
                mma16816(acc_o[nt], pl4, h0, h1);
                mma16816(acc_o[nt], pa, l0, l1);
            }
        }
        __syncthreads();
    }

    // ---- epilogue: normalize, write bf16 hi/lo O in [M_, D_] layout
    float inv0 = 1.f / li0, inv1 = 1.f / li1;
    int b = bh >> 4, h = bh & 15;
    int row0 = q0 + w * 16 + (l >> 2);
    size_t base0 = ((size_t)(b * S_ + row0)) * D_ + h * HD_ + (l & 3) * 2;
    size_t base1 = base0 + (size_t)8 * D_;
    #pragma unroll
    for (int nt = 0; nt < 8; nt++) {
        float o0 = acc_o[nt][0] * inv0, o1 = acc_o[nt][1] * inv0;
        float o2 = acc_o[nt][2] * inv1, o3 = acc_o[nt][3] * inv1;
        float p0 = bf16rt(o0), p1 = bf16rt(o1), p2 = bf16rt(o2), p3 = bf16rt(o3);
        *(u32*)&Oh[base0 + nt * 8] = bpack(p0, p1);
        *(u32*)&Ol[base0 + nt * 8] = bpack(o0 - p0, o1 - p1);
        *(u32*)&Oh[base1 + nt * 8] = bpack(p2, p3);
        *(u32*)&Ol[base1 + nt * 8] = bpack(o2 - p2, o3 - p3);
    }
}

// =====================================================================
extern "C" void kernel_launch(void* const* d_in, const int* in_sizes, int n_in,
                              void* d_out, int out_size)
{
    const float* query = (const float*)d_in[0];
    const float* key   = (const float*)d_in[1];
    const float* value = (const float*)d_in[2];
    const float* wq    = (const float*)d_in[3];
    const float* wk    = (const float*)d_in[4];
    const float* wv    = (const float*)d_in[5];
    const float* wo    = (const float*)d_in[6];
    const float* bo    = (const float*)d_in[7];
    float* out = (float*)d_out;

    __nv_bfloat16 *Qhp, *Qlp, *Khp, *Klp, *Vhp, *Vlp;
    __nv_bfloat16 *Ahp, *Alp, *Whp, *Wlp, *Ohp, *Olp;
    cudaGetSymbolAddress((void**)&Qhp, g_Qh);
    cudaGetSymbolAddress((void**)&Qlp, g_Ql);
    cudaGetSymbolAddress((void**)&Khp, g_Kh);
    cudaGetSymbolAddress((void**)&Klp, g_Kl);
    cudaGetSymbolAddress((void**)&Vhp, g_Vh);
    cudaGetSymbolAddress((void**)&Vlp, g_Vl);
    cudaGetSymbolAddress((void**)&Ahp, g_Ah);
    cudaGetSymbolAddress((void**)&Alp, g_Al);
    cudaGetSymbolAddress((void**)&Whp, g_Wh);
    cudaGetSymbolAddress((void**)&Wlp, g_Wl);
    cudaGetSymbolAddress((void**)&Ohp, g_Oh);
    cudaGetSymbolAddress((void**)&Olp, g_Ol);

    cudaFuncSetAttribute(gemm_mm<0>, cudaFuncAttributeMaxDynamicSharedMemorySize, GEMM_SMEM);
    cudaFuncSetAttribute(gemm_mm<1>, cudaFuncAttributeMaxDynamicSharedMemorySize, GEMM_SMEM);
    cudaFuncSetAttribute(attn_tc, cudaFuncAttributeMaxDynamicSharedMemorySize, ATTN_SMEM);

    const int nAct4 = (M_ * D_) / 4;
    const int nW4   = (D_ * D_) / 4;
    dim3 gg(D_ / 128, M_ / 128);   // (8, 64)

    // Q projection -> bf16 hi/lo [B,H,S,HD]
    split_bf16_kernel<<<nAct4 / 256, 256>>>(query, Ahp, Alp, nAct4);
    split_bf16_kernel<<<nW4 / 256, 256>>>(wq, Whp, Wlp, nW4);
    gemm_mm<1><<<gg, 256, GEMM_SMEM>>>(Ahp, Alp, Whp, Wlp, nullptr, nullptr, Qhp, Qlp);
    // K projection
    split_bf16_kernel<<<nAct4 / 256, 256>>>(key, Ahp, Alp, nAct4);
    split_bf16_kernel<<<nW4 / 256, 256>>>(wk, Whp, Wlp, nW4);
    gemm_mm<1><<<gg, 256, GEMM_SMEM>>>(Ahp, Alp, Whp, Wlp, nullptr, nullptr, Khp, Klp);
    // V projection
    split_bf16_kernel<<<nAct4 / 256, 256>>>(value, Ahp, Alp, nAct4);
    split_bf16_kernel<<<nW4 / 256, 256>>>(wv, Whp, Wlp, nW4);
    gemm_mm<1><<<gg, 256, GEMM_SMEM>>>(Ahp, Alp, Whp, Wlp, nullptr, nullptr, Vhp, Vlp);

    // tensor-core attention (writes bf16 hi/lo O)
    attn_tc<<<dim3(S_ / 128, B_ * H_), 256, ATTN_SMEM>>>(
        Qhp, Qlp, Khp, Klp, Vhp, Vlp, Ohp, Olp);

    // output projection + bias
    split_bf16_kernel<<<nW4 / 256, 256>>>(wo, Whp, Wlp, nW4);
    gemm_mm<0><<<gg, 256, GEMM_SMEM>>>(Ohp, Olp, Whp, Wlp, bo, out, nullptr, nullptr);
}

// round 15
// speedup vs baseline: 1.0009x; 1.0002x over previous
#include <cuda_runtime.h>
#include <cuda_bf16.h>
#include <math.h>

typedef unsigned long long ull_t;
typedef unsigned int u32;

#define B_  4
#define S_  2048
#define D_  1024
#define H_  16
#define HD_ 64
#define M_  (B_*S_)   // 8192

// ---------------- scratch (__device__ globals: allocation-free rule) ----------
__device__ __nv_bfloat16 g_Qh[(size_t)M_*D_];
__device__ __nv_bfloat16 g_Ql[(size_t)M_*D_];
__device__ __nv_bfloat16 g_Kh[(size_t)M_*D_];
__device__ __nv_bfloat16 g_Kl[(size_t)M_*D_];
__device__ __nv_bfloat16 g_Vh[(size_t)M_*D_];
__device__ __nv_bfloat16 g_Vl[(size_t)M_*D_];
__device__ __nv_bfloat16 g_Ah[(size_t)M_*D_];
__device__ __nv_bfloat16 g_Al[(size_t)M_*D_];
__device__ __nv_bfloat16 g_Wh[(size_t)D_*D_];
__device__ __nv_bfloat16 g_Wl[(size_t)D_*D_];
__device__ __nv_bfloat16 g_Oh[(size_t)M_*D_];
__device__ __nv_bfloat16 g_Ol[(size_t)M_*D_];

// ---------------- baseline-PTX tensor-core helpers (sm_80+, works on sm_103) --
__device__ __forceinline__ u32 smem_u32(const void* p) {
    u32 a; asm("{ .reg .u64 t; cvta.to.shared.u64 t, %1; cvt.u32.u64 %0, t; }" : "=r"(a) : "l"(p));
    return a;
}
__device__ __forceinline__ void ldm_x4(u32* r, u32 addr) {
    asm volatile("ldmatrix.sync.aligned.m8n8.x4.shared.b16 {%0,%1,%2,%3}, [%4];"
        : "=r"(r[0]), "=r"(r[1]), "=r"(r[2]), "=r"(r[3]) : "r"(addr));
}
__device__ __forceinline__ void ldm_x4t(u32* r, u32 addr) {
    asm volatile("ldmatrix.sync.aligned.m8n8.x4.trans.shared.b16 {%0,%1,%2,%3}, [%4];"
        : "=r"(r[0]), "=r"(r[1]), "=r"(r[2]), "=r"(r[3]) : "r"(addr));
}
__device__ __forceinline__ void mma16816(float* d, const u32* a, u32 b0, u32 b1) {
    asm volatile("mma.sync.aligned.m16n8k16.row.col.f32.bf16.bf16.f32 "
        "{%0,%1,%2,%3}, {%4,%5,%6,%7}, {%8,%9}, {%0,%1,%2,%3};"
        : "+f"(d[0]), "+f"(d[1]), "+f"(d[2]), "+f"(d[3])
        : "r"(a[0]), "r"(a[1]), "r"(a[2]), "r"(a[3]), "r"(b0), "r"(b1));
}
#define CP_ASYNC(dst, src) asm volatile("cp.async.cg.shared.global [%0], [%1], 16;" :: "r"(dst), "l"(src) : "memory")
#define CP_COMMIT()  asm volatile("cp.async.commit_group;" ::: "memory")
#define CP_WAIT(n)   asm volatile("cp.async.wait_group %0;" :: "n"(n) : "memory")

__device__ __forceinline__ float ex2f(float x) {
    float y; asm("ex2.approx.f32 %0, %1;" : "=f"(y) : "f"(x)); return y;
}
// pack two floats into bf16x2 (lo in low half, hi in high half)
__device__ __forceinline__ u32 bpack(float lo, float hi) {
    u32 r; asm("cvt.rn.bf16x2.f32 %0, %1, %2;" : "=r"(r) : "f"(hi), "f"(lo)); return r;
}
__device__ __forceinline__ float bf16rt(float x) {   // round-trip through bf16
    return __bfloat162float(__float2bfloat16(x));
}

// =====================================================================
// fp32 -> bf16 hi/lo split
// =====================================================================
__global__ void split_bf16_kernel(const float* __restrict__ x,
                                  __nv_bfloat16* __restrict__ hi,
                                  __nv_bfloat16* __restrict__ lo, int n4)
{
    int i = blockIdx.x * blockDim.x + threadIdx.x;
    if (i >= n4) return;
    float4 v = ((const float4*)x)[i];
    float f[4] = { v.x, v.y, v.z, v.w };
    union { __nv_bfloat16 b[4]; uint2 u; } Hh, Ll;
    #pragma unroll
    for (int j = 0; j < 4; j++) {
        __nv_bfloat16 h = __float2bfloat16(f[j]);
        Hh.b[j] = h;
        Ll.b[j] = __float2bfloat16(f[j] - __bfloat162float(h));
    }
    ((uint2*)hi)[i] = Hh.u;
    ((uint2*)lo)[i] = Ll.u;
}

// =====================================================================
// HMMA GEMM (mma.sync bf16, hi/lo 3-pass)
// MODE 0: C=[M_,D_] fp32 + bias.  MODE 1: bf16 hi/lo -> [B,H,S,HD].
// =====================================================================
#define SROW 40
#define TILEB (128 * SROW * 2)
#define BUFB  (4 * TILEB)
#define GEMM_SMEM (2 * BUFB + 128)

template<int MODE>
__global__ __launch_bounds__(256, 1)
void gemm_mm(const __nv_bfloat16* __restrict__ Ah, const __nv_bfloat16* __restrict__ Al,
             const __nv_bfloat16* __restrict__ Bh, const __nv_bfloat16* __restrict__ Bl,
             const float* __restrict__ bias, float* __restrict__ C,
             __nv_bfloat16* __restrict__ Ch, __nv_bfloat16* __restrict__ Cl)
{
    extern __shared__ char smem[];
    const u32 sbase = (smem_u32(smem) + 127) & ~127u;

    const int t = threadIdx.x;
    const int l = t & 31;
    const int warp = t >> 5;
    const int wm = warp >> 2, wn = warp & 3;
    const int m0 = blockIdx.y * 128;
    const int n0 = blockIdx.x * 128;

    const __nv_bfloat16* gp0 = Ah + (size_t)m0 * D_;
    const __nv_bfloat16* gp1 = Al + (size_t)m0 * D_;
    const __nv_bfloat16* gp2 = Bh + (size_t)n0 * D_;
    const __nv_bfloat16* gp3 = Bl + (size_t)n0 * D_;

    const u32 aoff = ((u32)(wm*64 + ((l & 7) + ((l >> 3) & 1) * 8)) * SROW + ((l >> 4) * 8)) * 2;
    const u32 boff = ((u32)(wn*32 + ((l & 7) + ((l >> 4) & 1) * 8)) * SROW + (((l >> 3) & 1) * 8)) * 2;

    float acc[4][4][4];
    #pragma unroll
    for (int i = 0; i < 4; i++)
        #pragma unroll
        for (int j = 0; j < 4; j++)
            #pragma unroll
            for (int q = 0; q < 4; q++) acc[i][j][q] = 0.f;

    auto cp_chunk = [&](int kc, int bufsel) {
        u32 db = sbase + (u32)bufsel * BUFB;
        #pragma unroll
        for (int i = 0; i < 8; i++) {
            int idx = t + (i & 1) * 256;
            int r = idx >> 2, c = idx & 3;
            size_t go = (size_t)r * D_ + kc + c * 8;
            u32 dst = db + (u32)(i >> 1) * TILEB + (u32)(r * SROW + c * 8) * 2;
            const __nv_bfloat16* src = (i < 2) ? gp0 : (i < 4) ? gp1 : (i < 6) ? gp2 : gp3;
            CP_ASYNC(dst, src + go);
        }
    };

    cp_chunk(0, 0);
    CP_COMMIT();

    const int NCH = D_ / 32;
    for (int kt = 0; kt < NCH; kt++) {
        int buf = kt & 1;
        if (kt + 1 < NCH) {
            cp_chunk((kt + 1) * 32, buf ^ 1);
            CP_COMMIT();
            CP_WAIT(1);
        } else {
            CP_WAIT(0);
        }
        __syncthreads();

        u32 aH = sbase + (u32)buf * BUFB;
        u32 bH = aH + 2 * TILEB;

        #pragma unroll
        for (int ks = 0; ks < 2; ks++) {
            u32 ah[4][4], al[4][4], bh[2][4], bl[2][4];
            #pragma unroll
            for (int mt = 0; mt < 4; mt++) {
                u32 ad = aH + aoff + (u32)(mt * 16 * SROW + ks * 16) * 2;
                ldm_x4(ah[mt], ad);
                ldm_x4(al[mt], ad + TILEB);
            }
            #pragma unroll
            for (int nt = 0; nt < 2; nt++) {
                u32 bd = bH + boff + (u32)(nt * 16 * SROW + ks * 16) * 2;
                ldm_x4(bh[nt], bd);
                ldm_x4(bl[nt], bd + TILEB);
            }
            #pragma unroll
            for (int mt = 0; mt < 4; mt++)
                #pragma unroll
                for (int j = 0; j < 4; j++) {
                    u32 h0 = bh[j >> 1][(j & 1) * 2], h1 = bh[j >> 1][(j & 1) * 2 + 1];
                    u32 l0 = bl[j >> 1][(j & 1) * 2], l1 = bl[j >> 1][(j & 1) * 2 + 1];
                    mma16816(acc[mt][j], ah[mt], h0, h1);
                    mma16816(acc[mt][j], al[mt], h0, h1);
                    mma16816(acc[mt][j], ah[mt], l0, l1);
                }
        }
        __syncthreads();
    }

    const int r0 = l >> 2, cp2 = (l & 3) * 2;
    #pragma unroll
    for (int mt = 0; mt < 4; mt++)
        #pragma unroll
        for (int j = 0; j < 4; j++) {
            int m = m0 + wm * 64 + mt * 16 + r0;
            int n = n0 + wn * 32 + j * 8 + cp2;
            if (MODE == 0) {
                float2 bb = *(const float2*)&bias[n];
                *(float2*)&C[(size_t)m * D_ + n] =
                    make_float2(acc[mt][j][0] + bb.x, acc[mt][j][1] + bb.y);
                *(float2*)&C[(size_t)(m + 8) * D_ + n] =
                    make_float2(acc[mt][j][2] + bb.x, acc[mt][j][3] + bb.y);
            } else {
                int h = n >> 6, d = n & 63;
                int b = m >> 11, s = m & 2047;
                size_t o = (((size_t)(b * H_ + h)) * S_ + s) * HD_ + d;
                #pragma unroll
                for (int rr = 0; rr < 2; rr++) {
                    float x0 = acc[mt][j][rr*2], x1 = acc[mt][j][rr*2+1];
                    float h0 = bf16rt(x0), h1 = bf16rt(x1);
                    size_t oo = o + (size_t)rr * 8 * HD_;
                    *(u32*)&Ch[oo] = bpack(h0, h1);
                    *(u32*)&Cl[oo] = bpack(x0 - h0, x1 - h1);
                }
            }
        }
}

// =====================================================================
// Tensor-core flash attention, bf16 hi/lo 3-pass.
// CTA: 128 q-rows of one (b,h). 8 warps x 16 q-rows. K-tiles of 64 keys.
// =====================================================================
#define SP   72                       // padded bf16 row stride
#define QT   (128 * SP * 2)           // 18432 B per Q array
#define KVT  (64 * SP * 2)            // 9216 B per K/V array
#define KVBUF (4 * KVT)               // 36864 B (Kh,Kl,Vh,Vl)
#define ATTN_SMEM (2 * QT + 2 * KVBUF + 128)   // 110720 B
#define CEXP 0.18033688011112042f     // 0.125 * log2(e)

__global__ __launch_bounds__(256, 1)
void attn_tc(const __nv_bfloat16* __restrict__ Qh, const __nv_bfloat16* __restrict__ Ql,
             const __nv_bfloat16* __restrict__ Kh, const __nv_bfloat16* __restrict__ Kl,
             const __nv_bfloat16* __restrict__ Vh, const __nv_bfloat16* __restrict__ Vl,
             __nv_bfloat16* __restrict__ Oh, __nv_bfloat16* __restrict__ Ol)
{
    extern __shared__ char smem[];
    const u32 sbase = (smem_u32(smem) + 127) & ~127u;
    const u32 sQh = sbase, sQl = sbase + QT, sKV = sbase + 2 * QT;

    const int t = threadIdx.x;
    const int l = t & 31;
    const int w = t >> 5;
    const int bh = blockIdx.y;
    const int q0 = blockIdx.x * 128;

    const __nv_bfloat16* qhp = Qh + ((size_t)bh * S_ + q0) * HD_;
    const __nv_bfloat16* qlp = Ql + ((size_t)bh * S_ + q0) * HD_;

    // Q load (both halves): 128 rows x 64 elems
    #pragma unroll
    for (int i = 0; i < 4; i++) {
        int idx = t + i * 256;
        int r = idx >> 3, c = idx & 7;
        u32 so = (u32)((r * SP + c * 8) * 2);
        size_t go = (size_t)r * HD_ + c * 8;
        CP_ASYNC(sQh + so, qhp + go);
        CP_ASYNC(sQl + so, qlp + go);
    }

    auto cp_kv = [&](int kt, int bufsel) {
        u32 db = sKV + (u32)bufsel * KVBUF;
        size_t gbase = (size_t)bh * S_ * HD_ + (size_t)kt * 64 * HD_;
        #pragma unroll
        for (int i = 0; i < 2; i++) {
            int idx = t + i * 256;
            int r = idx >> 3, c = idx & 7;
            u32 so = (u32)((r * SP + c * 8) * 2);
            size_t go = gbase + (size_t)r * HD_ + c * 8;
            CP_ASYNC(db + 0 * KVT + so, Kh + go);
            CP_ASYNC(db + 1 * KVT + so, Kl + go);
            CP_ASYNC(db + 2 * KVT + so, Vh + go);
            CP_ASYNC(db + 3 * KVT + so, Vl + go);
        }
    };

    cp_kv(0, 0);
    CP_COMMIT();

    // per-lane fragment offsets (bytes)
    const u32 aoff = (u32)(((w * 16 + (l & 15)) * SP + (l >> 4) * 8) * 2);
    const u32 koff = (u32)((((l & 7) + ((l >> 4) & 1) * 8) * SP + ((l >> 3) & 1) * 8) * 2);
    const u32 voff = (u32)((((l & 7) + ((l >> 3) & 1) * 8) * SP + ((l >> 4) & 1) * 8) * 2);

    float acc_o[8][4];
    #pragma unroll
    for (int i = 0; i < 8; i++)
        #pragma unroll
        for (int q = 0; q < 4; q++) acc_o[i][q] = 0.f;
    float mi0 = -1e30f, mi1 = -1e30f, li0 = 0.f, li1 = 0.f;

    const int NT = S_ / 64;   // 32
    for (int kt = 0; kt < NT; kt++) {
        int buf = kt & 1;
        if (kt + 1 < NT) {
            cp_kv(kt + 1, buf ^ 1);
            CP_COMMIT();
            CP_WAIT(1);
        } else {
            CP_WAIT(0);
        }
        __syncthreads();

        u32 kb = sKV + (u32)buf * KVBUF;

        // ---- S = Q K^T, 3-pass hi/lo. s[j] = n8 tile j over 64 keys.
        float s[8][4];
        #pragma unroll
        for (int j = 0; j < 8; j++)
            #pragma unroll
            for (int q = 0; q < 4; q++) s[j][q] = 0.f;

        #pragma unroll
        for (int ks = 0; ks < 4; ks++) {
            u32 qa[4], ql4[4], khf[4][4], klf[4][4];
            u32 ad = sQh + aoff + (u32)(ks * 32);
            ldm_x4(qa, ad);
            ldm_x4(ql4, ad + QT);
            #pragma unroll
            for (int nb = 0; nb < 4; nb++) {
                u32 bd = kb + koff + (u32)((nb * 16 * SP) * 2 + ks * 32);
                ldm_x4(khf[nb], bd);
                ldm_x4(klf[nb], bd + KVT);
            }
            #pragma unroll
            for (int j = 0; j < 8; j++) {
                u32 h0 = khf[j >> 1][(j & 1) * 2], h1 = khf[j >> 1][(j & 1) * 2 + 1];
                u32 l0 = klf[j >> 1][(j & 1) * 2], l1 = klf[j >> 1][(j & 1) * 2 + 1];
                mma16816(s[j], qa, h0, h1);
                mma16816(s[j], ql4, h0, h1);
                mma16816(s[j], qa, l0, l1);
            }
        }

        // ---- online softmax (lane owns rows r=l/4 and r+8; quad = 4 lanes/row)
        float mx0 = -1e30f, mx1 = -1e30f;
        #pragma unroll
        for (int j = 0; j < 8; j++) {
            mx0 = fmaxf(mx0, fmaxf(s[j][0], s[j][1]));
            mx1 = fmaxf(mx1, fmaxf(s[j][2], s[j][3]));
        }
        mx0 = fmaxf(mx0, __shfl_xor_sync(0xffffffffu, mx0, 1));
        mx0 = fmaxf(mx0, __shfl_xor_sync(0xffffffffu, mx0, 2));
        mx1 = fmaxf(mx1, __shfl_xor_sync(0xffffffffu, mx1, 1));
        mx1 = fmaxf(mx1, __shfl_xor_sync(0xffffffffu, mx1, 2));
        float mn0 = fmaxf(mi0, mx0), mn1 = fmaxf(mi1, mx1);
        float corr0 = ex2f(CEXP * (mi0 - mn0));
        float corr1 = ex2f(CEXP * (mi1 - mn1));
        mi0 = mn0; mi1 = mn1;

        float rs0 = 0.f, rs1 = 0.f;
        #pragma unroll
        for (int j = 0; j < 8; j++) {
            s[j][0] = ex2f(CEXP * (s[j][0] - mn0));
            s[j][1] = ex2f(CEXP * (s[j][1] - mn0));
            s[j][2] = ex2f(CEXP * (s[j][2] - mn1));
            s[j][3] = ex2f(CEXP * (s[j][3] - mn1));
            rs0 += s[j][0] + s[j][1];
            rs1 += s[j][2] + s[j][3];
        }
        rs0 += __shfl_xor_sync(0xffffffffu, rs0, 1);
        rs0 += __shfl_xor_sync(0xffffffffu, rs0, 2);
        rs1 += __shfl_xor_sync(0xffffffffu, rs1, 1);
        rs1 += __shfl_xor_sync(0xffffffffu, rs1, 2);
        li0 = li0 * corr0 + rs0;
        li1 = li1 * corr1 + rs1;

        #pragma unroll
        for (int i = 0; i < 8; i++) {
            acc_o[i][0] *= corr0; acc_o[i][1] *= corr0;
            acc_o[i][2] *= corr1; acc_o[i][3] *= corr1;
        }

        // ---- O += P V, 3-pass hi/lo (P from registers, V via ldmatrix.trans)
        u32 vb2 = kb + 2 * KVT + voff;
        #pragma unroll
        for (int ks = 0; ks < 4; ks++) {
            int j0 = 2 * ks, j1 = 2 * ks + 1;
            float h00 = bf16rt(s[j0][0]), h01 = bf16rt(s[j0][1]);
            float h02 = bf16rt(s[j0][2]), h03 = bf16rt(s[j0][3]);
            float h10 = bf16rt(s[j1][0]), h11 = bf16rt(s[j1][1]);
            float h12 = bf16rt(s[j1][2]), h13 = bf16rt(s[j1][3]);
            u32 pa[4], pl4[4];
            pa[0] = bpack(h00, h01);  pa[1] = bpack(h02, h03);
            pa[2] = bpack(h10, h11);  pa[3] = bpack(h12, h13);
            pl4[0] = bpack(s[j0][0]-h00, s[j0][1]-h01);
            pl4[1] = bpack(s[j0][2]-h02, s[j0][3]-h03);
            pl4[2] = bpack(s[j1][0]-h10, s[j1][1]-h11);
            pl4[3] = bpack(s[j1][2]-h12, s[j1][3]-h13);

            u32 vhf[4][4], vlf[4][4];
            #pragma unroll
            for (int nb = 0; nb < 4; nb++) {
                u32 vd = vb2 + (u32)((ks * 16 * SP) * 2 + nb * 32);
                ldm_x4t(vhf[nb], vd);
                ldm_x4t(vlf[nb], vd + KVT);
            }
            #pragma unroll
            for (int nt = 0; nt < 8; nt++) {
                u32 h0 = vhf[nt >> 1][(nt & 1) * 2], h1 = vhf[nt >> 1][(nt & 1) * 2 + 1];
                u32 l0 = vlf[nt >> 1][(nt & 1) * 2], l1 = vlf[nt >> 1][(nt & 1) * 2 + 1];
                mma16816(acc_o[nt], pa, h0, h1);
                mma16816(acc_o[nt], pl4, h0, h1);
                mma16816(acc_o[nt], pa, l0, l1);
            }
        }
        __syncthreads();
    }

    // ---- epilogue: normalize, write bf16 hi/lo O in [M_, D_] layout
    float inv0 = 1.f / li0, inv1 = 1.f / li1;
    int b = bh >> 4, h = bh & 15;
    int row0 = q0 + w * 16 + (l >> 2);
    size_t base0 = ((size_t)(b * S_ + row0)) * D_ + h * HD_ + (l & 3) * 2;
    size_t base1 = base0 + (size_t)8 * D_;
    #pragma unroll
    for (int nt = 0; nt < 8; nt++) {
        float o0 = acc_o[nt][0] * inv0, o1 = acc_o[nt][1] * inv0;
        float o2 = acc_o[nt][2] * inv1, o3 = acc_o[nt][3] * inv1;
        float p0 = bf16rt(o0), p1 = bf16rt(o1), p2 = bf16rt(o2), p3 = bf16rt(o3);
        *(u32*)&Oh[base0 + nt * 8] = bpack(p0, p1);
        *(u32*)&Ol[base0 + nt * 8] = bpack(o0 - p0, o1 - p1);
        *(u32*)&Oh[base1 + nt * 8] = bpack(p2, p3);
        *(u32*)&Ol[base1 + nt * 8] = bpack(o2 - p2, o3 - p3);
    }
}

// =====================================================================
extern "C" void kernel_launch(void* const* d_in, const int* in_sizes, int n_in,
                              void* d_out, int out_size)
{
    const float* query = (const float*)d_in[0];
    const float* key   = (const float*)d_in[1];
    const float* value = (const float*)d_in[2];
    const float* wq    = (const float*)d_in[3];
    const float* wk    = (const float*)d_in[4];
    const float* wv    = (const float*)d_in[5];
    const float* wo    = (const float*)d_in[6];
    const float* bo    = (const float*)d_in[7];
    float* out = (float*)d_out;

    __nv_bfloat16 *Qhp, *Qlp, *Khp, *Klp, *Vhp, *Vlp;
    __nv_bfloat16 *Ahp, *Alp, *Whp, *Wlp, *Ohp, *Olp;
    cudaGetSymbolAddress((void**)&Qhp, g_Qh);
    cudaGetSymbolAddress((void**)&Qlp, g_Ql);
    cudaGetSymbolAddress((void**)&Khp, g_Kh);
    cudaGetSymbolAddress((void**)&Klp, g_Kl);
    cudaGetSymbolAddress((void**)&Vhp, g_Vh);
    cudaGetSymbolAddress((void**)&Vlp, g_Vl);
    cudaGetSymbolAddress((void**)&Ahp, g_Ah);
    cudaGetSymbolAddress((void**)&Alp, g_Al);
    cudaGetSymbolAddress((void**)&Whp, g_Wh);
    cudaGetSymbolAddress((void**)&Wlp, g_Wl);
    cudaGetSymbolAddress((void**)&Ohp, g_Oh);
    cudaGetSymbolAddress((void**)&Olp, g_Ol);

    cudaFuncSetAttribute(gemm_mm<0>, cudaFuncAttributeMaxDynamicSharedMemorySize, GEMM_SMEM);
    cudaFuncSetAttribute(gemm_mm<1>, cudaFuncAttributeMaxDynamicSharedMemorySize, GEMM_SMEM);
    cudaFuncSetAttribute(attn_tc, cudaFuncAttributeMaxDynamicSharedMemorySize, ATTN_SMEM);

    const int nAct4 = (M_ * D_) / 4;
    const int nW4   = (D_ * D_) / 4;
    dim3 gg(D_ / 128, M_ / 128);   // (8, 64)

    // Q projection -> bf16 hi/lo [B,H,S,HD]
    split_bf16_kernel<<<nAct4 / 256, 256>>>(query, Ahp, Alp, nAct4);
    split_bf16_kernel<<<nW4 / 256, 256>>>(wq, Whp, Wlp, nW4);
    gemm_mm<1><<<gg, 256, GEMM_SMEM>>>(Ahp, Alp, Whp, Wlp, nullptr, nullptr, Qhp, Qlp);
    // K projection
    split_bf16_kernel<<<nAct4 / 256, 256>>>(key, Ahp, Alp, nAct4);
    split_bf16_kernel<<<nW4 / 256, 256>>>(wk, Whp, Wlp, nW4);
    gemm_mm<1><<<gg, 256, GEMM_SMEM>>>(Ahp, Alp, Whp, Wlp, nullptr, nullptr, Khp, Klp);
    // V projection
    split_bf16_kernel<<<nAct4 / 256, 256>>>(value, Ahp, Alp, nAct4);
    split_bf16_kernel<<<nW4 / 256, 256>>>(wv, Whp, Wlp, nW4);
    gemm_mm<1><<<gg, 256, GEMM_SMEM>>>(Ahp, Alp, Whp, Wlp, nullptr, nullptr, Vhp, Vlp);

    // tensor-core attention (writes bf16 hi/lo O)
    attn_tc<<<dim3(S_ / 128, B_ * H_), 256, ATTN_SMEM>>>(
        Qhp, Qlp, Khp, Klp, Vhp, Vlp, Ohp, Olp);

    // output projection + bias
    split_bf16_kernel<<<nW4 / 256, 256>>>(wo, Whp, Wlp, nW4);
    gemm_mm<0><<<gg, 256, GEMM_SMEM>>>(Ohp, Olp, Whp, Wlp, bo, out, nullptr, nullptr);
}